// round 12
// baseline (speedup 1.0000x reference)
#include <cuda_runtime.h>
#include <cuda_fp16.h>
#include <cstdint>

#define Bn 256
#define Sn 512
#define Kn 32
#define Fn 64
#define H1n 512
#define H2n 256

// ---------------- device scratch (allocation-free rule) ----------------
__device__ float    g_c1[Sn * H1n];
__device__ unsigned g_m[Bn * H2n];
__device__ __half   g_w1t[H1n * 2048];     // [n][k], k = nb*64+f
__device__ __half   g_w2t[H2n * H1n];      // [n2][h1]
__device__ __half   g_xr[Bn * Sn * Fn];
__device__ unsigned g_done;

// ---------------- smem layout (bytes) ----------------
// Stage: A (128 rows x 32 halves, 80B stride) + B (256 rows x 32 halves, 80B).
#define AROWB 80u
#define A_TILE (128u * AROWB)        // 10240
#define B_TILE (256u * AROWB)        // 20480
#define STGB   (A_TILE + B_TILE)     // 30720 per stage, 3 stages
#define HS_B   (3u * STGB)           // 92160
#define HROWB  1040u                 // 512 halves + 16B pad; 260 w == 4 mod 32
#define SMEM_BYTES (92160 + 128 * 1040)   // 225280

// ---------------- PTX helpers ----------------
__device__ __forceinline__ uint32_t smem_u32(const void* p) {
    uint32_t a;
    asm("{ .reg .u64 t; cvta.to.shared.u64 t, %1; cvt.u32.u64 %0, t; }" : "=r"(a) : "l"(p));
    return a;
}
__device__ __forceinline__ void cpasync16(uint32_t s, const void* g) {
    asm volatile("cp.async.cg.shared.global [%0], [%1], 16;" :: "r"(s), "l"(g));
}
#define CP_COMMIT() asm volatile("cp.async.commit_group;")
#define CP_WAIT1()  asm volatile("cp.async.wait_group 1;")

#define LDSM4(r0, r1, r2, r3, addr) \
    asm volatile("ldmatrix.sync.aligned.m8n8.x4.shared.b16 {%0,%1,%2,%3}, [%4];" \
        : "=r"(r0), "=r"(r1), "=r"(r2), "=r"(r3) : "r"(addr))

// fp16-accumulate HMMA: D(f16x2 pair) += A*B
__device__ __forceinline__ void mma16h(uint32_t& d0, uint32_t& d1, const uint32_t* a,
                                       uint32_t b0, uint32_t b1) {
    asm volatile(
        "mma.sync.aligned.m16n8k16.row.col.f16.f16.f16.f16 "
        "{%0,%1}, {%2,%3,%4,%5}, {%6,%7}, {%0,%1};"
        : "+r"(d0), "+r"(d1)
        : "r"(a[0]), "r"(a[1]), "r"(a[2]), "r"(a[3]), "r"(b0), "r"(b1));
}

// ---------------- merged prep kernel ----------------
#define PREP_BLOCKS 38144
__global__ void prep_all_kernel(const float* __restrict__ x,
                                const float* __restrict__ W1,
                                const float* __restrict__ b1,
                                const float* __restrict__ W2,
                                const float* __restrict__ dist) {
    const int blk = blockIdx.x, t = threadIdx.x;
    if (blk < 32768) {
        int i = blk * 256 + t;
        g_xr[i] = __float2half_rn(x[i]);
    } else if (blk < 36864) {
        int idx = (blk - 32768) * 256 + t;
        int k = idx & 2047, n = idx >> 11;
        int row = (k >> 6) * 65 + (k & 63);
        g_w1t[(size_t)n * 2048 + k] = __float2half_rn(W1[(size_t)row * H1n + n]);
    } else if (blk < 37376) {
        int idx = (blk - 36864) * 256 + t;
        int h = idx & 511, n = idx >> 9;
        g_w2t[(size_t)n * H1n + h] = __float2half_rn(W2[(size_t)h * H2n + n]);
    } else if (blk < 37888) {
        int s = blk - 37376;
#pragma unroll
        for (int hh = 0; hh < 2; hh++) {
            int h = t + hh * 256;
            float acc = b1[h];
#pragma unroll
            for (int k = 0; k < Kn; k++)
                acc = fmaf(dist[s * Kn + k], W1[(k * 65 + 64) * H1n + h], acc);
            g_c1[s * H1n + h] = acc;
        }
    } else {
        int i = (blk - 37888) * 256 + t;
        g_m[i] = 0u;
        if (blk == 37888 && t == 0) g_done = 0u;
    }
}

// ---------------- load helpers (256 threads) ----------------
// GEMM1 chunk c (k = c*32..+32): neighbor c>>1, f-half c&1. Ntile = 256.
__device__ __forceinline__ void issue_g1(int c, int n1, int st, int tid,
                                         uint32_t smb, const int* __restrict__ nbh_s,
                                         int b0) {
    const int sidx = __ldg(&nbh_s[c >> 1]);
    const int f0 = (c & 1) * 32;
    const uint32_t ab = smb + (uint32_t)st * STGB;
    const __half* asrc = g_xr + ((size_t)b0 * Sn + sidx) * Fn + f0;
#pragma unroll
    for (int p = 0; p < 2; p++) {
        int u = tid + p * 256; int r = u >> 2, q = u & 3;
        cpasync16(ab + (uint32_t)r * AROWB + (uint32_t)q * 16u,
                  asrc + (size_t)r * (Sn * Fn) + q * 8);
    }
    const uint32_t bb = ab + A_TILE;
    const __half* bsrc = g_w1t + (size_t)(n1 * 256) * 2048 + c * 32;
#pragma unroll
    for (int p = 0; p < 4; p++) {
        int u = tid + p * 256; int r = u >> 2, q = u & 3;
        cpasync16(bb + (uint32_t)r * AROWB + (uint32_t)q * 16u,
                  bsrc + (size_t)r * 2048 + q * 8);
    }
}
__device__ __forceinline__ void issue_g2(int kc, int st, int tid, uint32_t smb) {
    const uint32_t bb = smb + (uint32_t)st * STGB + A_TILE;
    const __half* bsrc = g_w2t + kc * 32;
#pragma unroll
    for (int p = 0; p < 4; p++) {
        int u = tid + p * 256; int r = u >> 2, q = u & 3;
        cpasync16(bb + (uint32_t)r * AROWB + (uint32_t)q * 16u,
                  bsrc + (size_t)r * H1n + q * 8);
    }
}
// unified ord dispatch: ord 0..127 GEMM1 (n1 = ord>>6, c = ord&63), 128..143 GEMM2
__device__ __forceinline__ void issue_ord(int o, int tid, uint32_t smb,
                                          const int* __restrict__ nbh_s, int b0) {
    if (o < 128)      issue_g1(o & 63, o >> 6, o % 3, tid, smb, nbh_s, b0);
    else if (o < 144) issue_g2(o - 128, o % 3, tid, smb);
    CP_COMMIT();
}

// promote f16 accs into f32 shadow (call at window end)
__device__ __forceinline__ void promote(float sh[4][8][4], uint32_t ah[4][8][2]) {
#pragma unroll
    for (int mt = 0; mt < 4; mt++)
#pragma unroll
        for (int nt = 0; nt < 8; nt++) {
            float2 f0 = __half22float2(*(__half2*)&ah[mt][nt][0]);
            float2 f1 = __half22float2(*(__half2*)&ah[mt][nt][1]);
            sh[mt][nt][0] += f0.x; sh[mt][nt][1] += f0.y;
            sh[mt][nt][2] += f1.x; sh[mt][nt][3] += f1.y;
        }
}
__device__ __forceinline__ void zero_ah(uint32_t ah[4][8][2]) {
#pragma unroll
    for (int mt = 0; mt < 4; mt++)
#pragma unroll
        for (int nt = 0; nt < 8; nt++) { ah[mt][nt][0] = 0u; ah[mt][nt][1] = 0u; }
}

// ---------------- fused fp16 mma kernel, 256 threads, f16-acc ----------------
__global__ __launch_bounds__(256, 1)
void fused_mma_kernel(const int* __restrict__ nbh, const float* __restrict__ b2,
                      const float* __restrict__ Wd, const float* __restrict__ bd,
                      float* __restrict__ out) {
    extern __shared__ char smc[];
    const int tid = threadIdx.x, lane = tid & 31, wid = tid >> 5;
    const int gid = lane >> 2, tig = lane & 3;
    const int wm  = (wid >> 2) * 64;    // warp M offset (0 or 64)
    const int wnc = wid & 3;            // warp N col (0..3), 64 each
    const int s = blockIdx.y, b0 = blockIdx.x * 128;
    const int* nbh_s = nbh + s * Kn;
    const uint32_t smb = smem_u32(smc);

    const uint32_t a_lrow = (uint32_t)(lane & 15) * AROWB + (uint32_t)(lane >> 4) * 16u;
    const int bg = lane >> 3;
    const uint32_t b_lrow = (uint32_t)(((bg >> 1) * 8) + (lane & 7)) * AROWB
                          + (uint32_t)(bg & 1) * 16u;
    const uint32_t h_lrow = (uint32_t)(lane & 15) * HROWB + (uint32_t)(lane >> 4) * 16u;

    // prologue: chunks 0,1 in flight (distance 2, 3-stage ring, WAIT1)
    issue_ord(0, tid, smb, nbh_s, b0);
    issue_ord(1, tid, smb, nbh_s, b0);

    // ================= Phase 1: h1 = relu(gather @ W1 + c1) -> Hs =================
    for (int n1 = 0; n1 < 2; n1++) {
        float    sh[4][8][4];
        uint32_t ah[4][8][2];
#pragma unroll
        for (int mt = 0; mt < 4; mt++)
#pragma unroll
            for (int nt = 0; nt < 8; nt++)
#pragma unroll
                for (int i = 0; i < 4; i++) sh[mt][nt][i] = 0.f;

        for (int c = 0; c < 64; c++) {
            const int ord = n1 * 64 + c;
            CP_WAIT1();
            __syncthreads();
            issue_ord(ord + 2, tid, smb, nbh_s, b0);

            if ((c & 3) == 0) zero_ah(ah);   // K=128 window start

            const uint32_t stb = smb + (uint32_t)(ord % 3) * STGB;
            const uint32_t aT = stb + (uint32_t)wm * AROWB + a_lrow;
            const uint32_t bT = stb + A_TILE + (uint32_t)(wnc * 64) * AROWB + b_lrow;
#pragma unroll
            for (int ks = 0; ks < 2; ks++) {
                uint32_t a[4][4];
#pragma unroll
                for (int mt = 0; mt < 4; mt++)
                    LDSM4(a[mt][0], a[mt][1], a[mt][2], a[mt][3],
                          aT + (uint32_t)mt * (16 * AROWB) + ks * 32);
#pragma unroll
                for (int j = 0; j < 4; j++) {
                    uint32_t r0, r1, r2, r3;
                    LDSM4(r0, r1, r2, r3, bT + (uint32_t)j * (16 * AROWB) + ks * 32);
#pragma unroll
                    for (int mt = 0; mt < 4; mt++) {
                        mma16h(ah[mt][2 * j][0],     ah[mt][2 * j][1],     a[mt], r0, r1);
                        mma16h(ah[mt][2 * j + 1][0], ah[mt][2 * j + 1][1], a[mt], r2, r3);
                    }
                }
            }
            if ((c & 3) == 3) promote(sh, ah);   // K=128 window end
        }

        // epilogue: relu(sh + c1) -> fp16 -> Hs cols [n1*256..+256)
        const float* c1p = g_c1 + s * H1n + n1 * 256;
#pragma unroll
        for (int nt = 0; nt < 8; nt++) {
            const int col = wnc * 64 + nt * 8 + tig * 2;
            const float2 cv = __ldg((const float2*)(c1p + col));
            const uint32_t colb = (uint32_t)(n1 * 256 + col) * 2u;
#pragma unroll
            for (int mt = 0; mt < 4; mt++) {
                const int r = wm + mt * 16 + gid;
                __half2* h0  = (__half2*)(smc + HS_B + (uint32_t)r * HROWB + colb);
                __half2* h1r = (__half2*)(smc + HS_B + (uint32_t)(r + 8) * HROWB + colb);
                *h0  = __floats2half2_rn(fmaxf(sh[mt][nt][0] + cv.x, 0.f),
                                         fmaxf(sh[mt][nt][1] + cv.y, 0.f));
                *h1r = __floats2half2_rn(fmaxf(sh[mt][nt][2] + cv.x, 0.f),
                                         fmaxf(sh[mt][nt][3] + cv.y, 0.f));
            }
        }
    }

    // ================= Phase 2: h2 = Hs @ W2t^T (k=512, 16 chunks) =================
    {
        float    sh[4][8][4];
        uint32_t ah[4][8][2];
#pragma unroll
        for (int mt = 0; mt < 4; mt++)
#pragma unroll
            for (int nt = 0; nt < 8; nt++)
#pragma unroll
                for (int i = 0; i < 4; i++) sh[mt][nt][i] = 0.f;

        for (int kc = 0; kc < 16; kc++) {
            const int ord = 128 + kc;
            CP_WAIT1();
            __syncthreads();   // W2 chunk visible; kc=0 also fences Hs writes
            issue_ord(ord + 2, tid, smb, nbh_s, b0);

            if ((kc & 1) == 0) zero_ah(ah);   // K=64 window start

            const uint32_t aT = smb + HS_B + (uint32_t)wm * HROWB + h_lrow
                              + (uint32_t)kc * 64u;
            const uint32_t bT = smb + (uint32_t)(ord % 3) * STGB + A_TILE
                              + (uint32_t)(wnc * 64) * AROWB + b_lrow;
#pragma unroll
            for (int ks = 0; ks < 2; ks++) {
                uint32_t a[4][4];
#pragma unroll
                for (int mt = 0; mt < 4; mt++)
                    LDSM4(a[mt][0], a[mt][1], a[mt][2], a[mt][3],
                          aT + (uint32_t)mt * (16 * HROWB) + ks * 32);
#pragma unroll
                for (int j = 0; j < 4; j++) {
                    uint32_t r0, r1, r2, r3;
                    LDSM4(r0, r1, r2, r3, bT + (uint32_t)j * (16 * AROWB) + ks * 32);
#pragma unroll
                    for (int mt = 0; mt < 4; mt++) {
                        mma16h(ah[mt][2 * j][0],     ah[mt][2 * j][1],     a[mt], r0, r1);
                        mma16h(ah[mt][2 * j + 1][0], ah[mt][2 * j + 1][1], a[mt], r2, r3);
                    }
                }
            }
            if ((kc & 1) == 1) promote(sh, ah);   // K=64 window end
        }

        // epilogue: relu(sh + b2) -> atomicMax
#pragma unroll
        for (int nt = 0; nt < 8; nt++) {
            const int n2 = wnc * 64 + nt * 8 + tig * 2;
            const float2 bv = __ldg((const float2*)(b2 + n2));
#pragma unroll
            for (int mt = 0; mt < 4; mt++) {
                const int r = b0 + wm + mt * 16 + gid;
                float v0 = fmaxf(sh[mt][nt][0] + bv.x, 0.f);
                float v1 = fmaxf(sh[mt][nt][1] + bv.y, 0.f);
                float v2 = fmaxf(sh[mt][nt][2] + bv.x, 0.f);
                float v3 = fmaxf(sh[mt][nt][3] + bv.y, 0.f);
                atomicMax(&g_m[r * H2n + n2],           __float_as_uint(v0));
                atomicMax(&g_m[r * H2n + n2 + 1],       __float_as_uint(v1));
                atomicMax(&g_m[(r + 8) * H2n + n2],     __float_as_uint(v2));
                atomicMax(&g_m[(r + 8) * H2n + n2 + 1], __float_as_uint(v3));
            }
        }
    }

    // -------- inline finalize: last block computes out --------
    __threadfence();
    __shared__ unsigned s_last;
    if (tid == 0) {
        unsigned v = atomicAdd(&g_done, 1u);
        s_last = (v == 1023u) ? 1u : 0u;
    }
    __syncthreads();
    if (s_last) {
        const float bdv = __ldg(&bd[0]);
        for (int bb = 0; bb < 32; bb++) {
            const int b = wid * 32 + bb;
            float acc = 0.f;
#pragma unroll
            for (int q = 0; q < 8; q++) {
                const int n = q * 32 + lane;
                acc += __uint_as_float(__ldcg(&g_m[b * H2n + n])) * __ldg(&Wd[n]);
            }
#pragma unroll
            for (int off = 16; off; off >>= 1)
                acc += __shfl_xor_sync(0xFFFFFFFFu, acc, off);
            if (lane == 0) out[b] = acc + bdv;
        }
    }
}

extern "C" void kernel_launch(void* const* d_in, const int* in_sizes, int n_in,
                              void* d_out, int out_size) {
    const float* x    = (const float*)d_in[0];
    const int*   nbh  = (const int*)  d_in[1];
    const float* dist = (const float*)d_in[2];
    const float* W1   = (const float*)d_in[3];
    const float* b1   = (const float*)d_in[4];
    const float* W2   = (const float*)d_in[5];
    const float* b2   = (const float*)d_in[6];
    const float* Wd   = (const float*)d_in[7];
    const float* bd   = (const float*)d_in[8];
    float* out = (float*)d_out;

    static bool attr_set = false;
    if (!attr_set) {
        cudaFuncSetAttribute(fused_mma_kernel,
                             cudaFuncAttributeMaxDynamicSharedMemorySize, SMEM_BYTES);
        attr_set = true;
    }

    prep_all_kernel<<<PREP_BLOCKS, 256>>>(x, W1, b1, W2, dist);
    fused_mma_kernel<<<dim3(2, Sn), 256, SMEM_BYTES>>>(nbh, b2, Wd, bd, out);
}

// round 13
// speedup vs baseline: 1.2672x; 1.2672x over previous
#include <cuda_runtime.h>
#include <cuda_fp16.h>
#include <cstdint>

#define Bn 256
#define Sn 512
#define Kn 32
#define Fn 64
#define H1n 512
#define H2n 256

// ---------------- device scratch (allocation-free rule) ----------------
__device__ float    g_c1[Sn * H1n];        // fp32: b1 + dist-column contribution
__device__ unsigned g_m[Bn * H2n];         // bits of max_s relu(h2)
__device__ __half   g_w1t[H1n * 2048];     // [n][k], k = nb*64+f, fp16
__device__ __half   g_w2t[H2n * H1n];      // [n2][h1], fp16
__device__ __half   g_xr[Bn * Sn * Fn];    // fp16 x

// ---------------- smem layout (bytes) ----------------
#define ROWB 144u
#define TILEB (128u * ROWB)          // 18432
#define STGB  (2u * TILEB)           // 36864 per stage (A at +0, B at +TILEB)
#define HS_B  (3u * STGB)            // 110592
#define HROWB 272u                   // 128 halves data + pad
#define SMEM_BYTES (110592 + 128 * 272)   // 145408

// ---------------- PTX helpers ----------------
__device__ __forceinline__ uint32_t smem_u32(const void* p) {
    uint32_t a;
    asm("{ .reg .u64 t; cvta.to.shared.u64 t, %1; cvt.u32.u64 %0, t; }" : "=r"(a) : "l"(p));
    return a;
}
__device__ __forceinline__ void cpasync16(uint32_t s, const void* g) {
    asm volatile("cp.async.cg.shared.global [%0], [%1], 16;" :: "r"(s), "l"(g));
}
#define CP_COMMIT() asm volatile("cp.async.commit_group;")
#define CP_WAIT1()  asm volatile("cp.async.wait_group 1;")
#define CP_WAIT0()  asm volatile("cp.async.wait_group 0;")

#define LDSM4(r0, r1, r2, r3, addr) \
    asm volatile("ldmatrix.sync.aligned.m8n8.x4.shared.b16 {%0,%1,%2,%3}, [%4];" \
        : "=r"(r0), "=r"(r1), "=r"(r2), "=r"(r3) : "r"(addr))

__device__ __forceinline__ void mma16(float* d, const uint32_t* a,
                                      uint32_t b0, uint32_t b1) {
    asm volatile(
        "mma.sync.aligned.m16n8k16.row.col.f32.f16.f16.f32 "
        "{%0,%1,%2,%3}, {%4,%5,%6,%7}, {%8,%9}, {%0,%1,%2,%3};"
        : "+f"(d[0]), "+f"(d[1]), "+f"(d[2]), "+f"(d[3])
        : "r"(a[0]), "r"(a[1]), "r"(a[2]), "r"(a[3]), "r"(b0), "r"(b1));
}

// ---------------- merged prep kernel (one launch) ----------------
// Flat grid of 256-thread blocks:
//   [0, 8192)       : xr  (8,388,608 elems, 4/thread via float4)
//   [8192, 12288)   : w1t (1,048,576 elems, transpose gather)
//   [12288, 12800)  : w2t (131,072 elems, transpose gather)
//   [12800, 13312)  : c1  (one block per s, 2 h per thread)
//   [13312, 13568)  : zero g_m (65,536)
#define PREP_BLOCKS 13568
__global__ void prep_all_kernel(const float* __restrict__ x,
                                const float* __restrict__ W1,
                                const float* __restrict__ b1,
                                const float* __restrict__ W2,
                                const float* __restrict__ dist) {
    const int blk = blockIdx.x, t = threadIdx.x;
    if (blk < 8192) {
        int i = blk * 256 + t;               // float4 index
        float4 v = ((const float4*)x)[i];
        __half2 lo = __floats2half2_rn(v.x, v.y);
        __half2 hi = __floats2half2_rn(v.z, v.w);
        ((__half2*)g_xr)[i * 2]     = lo;
        ((__half2*)g_xr)[i * 2 + 1] = hi;
    } else if (blk < 12288) {
        int idx = (blk - 8192) * 256 + t;    // 512*2048
        int k = idx & 2047, n = idx >> 11;
        int row = (k >> 6) * 65 + (k & 63);
        g_w1t[(size_t)n * 2048 + k] = __float2half_rn(W1[(size_t)row * H1n + n]);
    } else if (blk < 12800) {
        int idx = (blk - 12288) * 256 + t;   // 256*512
        int h = idx & 511, n = idx >> 9;
        g_w2t[(size_t)n * H1n + h] = __float2half_rn(W2[(size_t)h * H2n + n]);
    } else if (blk < 13312) {
        int s = blk - 12800;
#pragma unroll
        for (int hh = 0; hh < 2; hh++) {
            int h = t + hh * 256;
            float acc = b1[h];
#pragma unroll
            for (int k = 0; k < Kn; k++)
                acc = fmaf(dist[s * Kn + k], W1[(k * 65 + 64) * H1n + h], acc);
            g_c1[s * H1n + h] = acc;
        }
    } else {
        int i = (blk - 13312) * 256 + t;
        g_m[i] = 0u;
    }
}

// ---------------- load helpers (256 threads) — R8 verbatim ----------------
__device__ __forceinline__ void issue_g1(int c, int n1, int st, int tid,
                                         uint32_t smb, const int* __restrict__ nbh_s,
                                         int b0) {
    const int sidx = __ldg(&nbh_s[c]);
    const uint32_t ab = smb + (uint32_t)st * STGB;
    const __half* asrc = g_xr + ((size_t)b0 * Sn + sidx) * Fn;
#pragma unroll
    for (int p = 0; p < 4; p++) {
        int u = tid + p * 256; int r = u >> 3, q = u & 7;
        cpasync16(ab + (uint32_t)r * ROWB + (uint32_t)q * 16u,
                  asrc + (size_t)r * (Sn * Fn) + q * 8);
    }
    const uint32_t bb = ab + TILEB;
    const __half* bsrc = g_w1t + (size_t)(n1 * 128) * 2048 + c * 64;
#pragma unroll
    for (int p = 0; p < 4; p++) {
        int u = tid + p * 256; int r = u >> 3, q = u & 7;
        cpasync16(bb + (uint32_t)r * ROWB + (uint32_t)q * 16u,
                  bsrc + (size_t)r * 2048 + q * 8);
    }
}
__device__ __forceinline__ void issue_g2(int n1, int hk, int st, int tid,
                                         uint32_t smb) {
    const uint32_t bb = smb + (uint32_t)st * STGB;
    const __half* bsrc = g_w2t + n1 * 128 + hk * 64;
#pragma unroll
    for (int p = 0; p < 8; p++) {
        int u = tid + p * 256; int n = u >> 3, q = u & 7;
        cpasync16(bb + (uint32_t)n * ROWB + (uint32_t)q * 16u,
                  bsrc + (size_t)n * H1n + q * 8);
    }
}

// ---------------- fused fp16 mma kernel — R8 verbatim ----------------
__global__ __launch_bounds__(256, 1)
void fused_mma_kernel(const int* __restrict__ nbh, const float* __restrict__ b2) {
    extern __shared__ char smc[];
    const int tid = threadIdx.x, lane = tid & 31, wid = tid >> 5;
    const int gid = lane >> 2, tig = lane & 3;
    const int wm = (wid >> 1) * 32;
    const int wn = wid & 1;
    const int s = blockIdx.y, b0 = blockIdx.x * 128;
    const int* nbh_s = nbh + s * Kn;
    const uint32_t smb = smem_u32(smc);

    const uint32_t a_lrow = (uint32_t)(lane & 15) * ROWB + (uint32_t)(lane >> 4) * 16u;
    const int bg = lane >> 3;
    const uint32_t b_lrow = (uint32_t)(((bg >> 1) * 8) + (lane & 7)) * ROWB
                          + (uint32_t)(bg & 1) * 16u;
    const uint32_t h_lrow = (uint32_t)(lane & 15) * HROWB + (uint32_t)(lane >> 4) * 16u;

    float acc2[2][16][4];
#pragma unroll
    for (int mt = 0; mt < 2; mt++)
#pragma unroll
        for (int nt = 0; nt < 16; nt++)
#pragma unroll
            for (int i = 0; i < 4; i++) acc2[mt][nt][i] = 0.f;

    for (int n1 = 0; n1 < 4; n1++) {
        float acc1[2][8][4];
#pragma unroll
        for (int mt = 0; mt < 2; mt++)
#pragma unroll
            for (int nt = 0; nt < 8; nt++)
#pragma unroll
                for (int i = 0; i < 4; i++) acc1[mt][nt][i] = 0.f;

        __syncthreads();
        issue_g1(0, n1, 0, tid, smb, nbh_s, b0);
        CP_COMMIT();
        issue_g1(1, n1, 1, tid, smb, nbh_s, b0);
        CP_COMMIT();

        for (int c = 0; c < 32; c++) {
            CP_WAIT1();
            __syncthreads();
            if (c < 30)       issue_g1(c + 2, n1, (c + 2) % 3, tid, smb, nbh_s, b0);
            else if (c == 30) issue_g2(n1, 0, 2, tid, smb);
            else              issue_g2(n1, 1, 0, tid, smb);
            CP_COMMIT();

            const uint32_t stb = smb + (uint32_t)(c % 3) * STGB;
            const uint32_t aT = stb + (uint32_t)wm * ROWB + a_lrow;
            const uint32_t bT = stb + TILEB + (uint32_t)(wn * 64) * ROWB + b_lrow;
#pragma unroll
            for (int ks = 0; ks < 4; ks++) {
                uint32_t a0[4], a1[4];
                LDSM4(a0[0], a0[1], a0[2], a0[3], aT + ks * 32);
                LDSM4(a1[0], a1[1], a1[2], a1[3], aT + 16 * ROWB + ks * 32);
#pragma unroll
                for (int j = 0; j < 4; j++) {
                    uint32_t r0, r1, r2, r3;
                    LDSM4(r0, r1, r2, r3, bT + (uint32_t)j * (16 * ROWB) + ks * 32);
                    mma16(acc1[0][2 * j],     a0, r0, r1);
                    mma16(acc1[0][2 * j + 1], a0, r2, r3);
                    mma16(acc1[1][2 * j],     a1, r0, r1);
                    mma16(acc1[1][2 * j + 1], a1, r2, r3);
                }
            }
        }

        {
            const float* c1p = g_c1 + s * H1n + n1 * 128;
#pragma unroll
            for (int nt = 0; nt < 8; nt++) {
                const int col = wn * 64 + nt * 8 + tig * 2;
                const float2 cv = __ldg((const float2*)(c1p + col));
#pragma unroll
                for (int mt = 0; mt < 2; mt++) {
                    const int r = wm + mt * 16 + gid;
                    __half2* h0 = (__half2*)(smc + HS_B + (uint32_t)r * HROWB + col * 2);
                    __half2* h1r = (__half2*)(smc + HS_B + (uint32_t)(r + 8) * HROWB + col * 2);
                    *h0  = __floats2half2_rn(fmaxf(acc1[mt][nt][0] + cv.x, 0.f),
                                             fmaxf(acc1[mt][nt][1] + cv.y, 0.f));
                    *h1r = __floats2half2_rn(fmaxf(acc1[mt][nt][2] + cv.x, 0.f),
                                             fmaxf(acc1[mt][nt][3] + cv.y, 0.f));
                }
            }
        }

#pragma unroll
        for (int kc = 0; kc < 2; kc++) {
            if (kc == 0) CP_WAIT1(); else CP_WAIT0();
            __syncthreads();
            const uint32_t aT = smb + HS_B + (uint32_t)wm * HROWB + h_lrow
                              + (uint32_t)kc * 128u;
            const uint32_t bT = smb + (uint32_t)(kc == 0 ? 2 : 0) * STGB
                              + (uint32_t)(wn * 128) * ROWB + b_lrow;
#pragma unroll
            for (int ks = 0; ks < 4; ks++) {
                uint32_t a0[4], a1[4];
                LDSM4(a0[0], a0[1], a0[2], a0[3], aT + ks * 32);
                LDSM4(a1[0], a1[1], a1[2], a1[3], aT + 16 * HROWB + ks * 32);
#pragma unroll
                for (int j = 0; j < 8; j++) {
                    uint32_t r0, r1, r2, r3;
                    LDSM4(r0, r1, r2, r3, bT + (uint32_t)j * (16 * ROWB) + ks * 32);
                    mma16(acc2[0][2 * j],     a0, r0, r1);
                    mma16(acc2[0][2 * j + 1], a0, r2, r3);
                    mma16(acc2[1][2 * j],     a1, r0, r1);
                    mma16(acc2[1][2 * j + 1], a1, r2, r3);
                }
            }
        }
    }

#pragma unroll
    for (int nt = 0; nt < 16; nt++) {
        const int n2 = wn * 128 + nt * 8 + tig * 2;
        const float2 bv = __ldg((const float2*)(b2 + n2));
#pragma unroll
        for (int mt = 0; mt < 2; mt++) {
            const int r = b0 + wm + mt * 16 + gid;
            float v0 = fmaxf(acc2[mt][nt][0] + bv.x, 0.f);
            float v1 = fmaxf(acc2[mt][nt][1] + bv.y, 0.f);
            float v2 = fmaxf(acc2[mt][nt][2] + bv.x, 0.f);
            float v3 = fmaxf(acc2[mt][nt][3] + bv.y, 0.f);
            atomicMax(&g_m[r * H2n + n2],           __float_as_uint(v0));
            atomicMax(&g_m[r * H2n + n2 + 1],       __float_as_uint(v1));
            atomicMax(&g_m[(r + 8) * H2n + n2],     __float_as_uint(v2));
            atomicMax(&g_m[(r + 8) * H2n + n2 + 1], __float_as_uint(v3));
        }
    }
}

// ---------------- finalize (separate tiny launch, as in R8) ----------------
__global__ void finalize_kernel(const float* __restrict__ Wd,
                                const float* __restrict__ bd,
                                float* __restrict__ out) {
    __shared__ float red[256];
    const int b = blockIdx.x, t = threadIdx.x;
    red[t] = __uint_as_float(g_m[b * H2n + t]) * Wd[t];
    __syncthreads();
#pragma unroll
    for (int st = 128; st > 0; st >>= 1) {
        if (t < st) red[t] += red[t + st];
        __syncthreads();
    }
    if (t == 0) out[b] = red[0] + bd[0];
}

extern "C" void kernel_launch(void* const* d_in, const int* in_sizes, int n_in,
                              void* d_out, int out_size) {
    const float* x    = (const float*)d_in[0];
    const int*   nbh  = (const int*)  d_in[1];
    const float* dist = (const float*)d_in[2];
    const float* W1   = (const float*)d_in[3];
    const float* b1   = (const float*)d_in[4];
    const float* W2   = (const float*)d_in[5];
    const float* b2   = (const float*)d_in[6];
    const float* Wd   = (const float*)d_in[7];
    const float* bd   = (const float*)d_in[8];
    float* out = (float*)d_out;

    static bool attr_set = false;
    if (!attr_set) {
        cudaFuncSetAttribute(fused_mma_kernel,
                             cudaFuncAttributeMaxDynamicSharedMemorySize, SMEM_BYTES);
        attr_set = true;
    }

    prep_all_kernel<<<PREP_BLOCKS, 256>>>(x, W1, b1, W2, dist);
    fused_mma_kernel<<<dim3(2, Sn), 256, SMEM_BYTES>>>(nbh, b2);
    finalize_kernel<<<Bn, H2n>>>(Wd, bd, out);
}

// round 15
// speedup vs baseline: 1.2738x; 1.0052x over previous
#include <cuda_runtime.h>
#include <cuda_fp16.h>
#include <cstdint>

#define Bn 256
#define Sn 512
#define Kn 32
#define Fn 64
#define H1n 512
#define H2n 256

// ---------------- device scratch (allocation-free rule) ----------------
__device__ float    g_c1[Sn * H1n];        // fp32: b1 + dist-column contribution
__device__ unsigned g_m[Bn * H2n];         // bits of max_s relu(h2)
__device__ __half   g_w1t[H1n * 2048];     // [n][k], k = nb*64+f, fp16
__device__ __half   g_w2t[H2n * H1n];      // [n2][h1], fp16
__device__ __half   g_xr[Bn * Sn * Fn];    // fp16 x

// ---------------- smem layout (bytes) ----------------
#define ROWB 144u
#define TILEB (128u * ROWB)          // 18432
#define STGB  (2u * TILEB)           // 36864 per stage (A at +0, B at +TILEB)
#define HS_B  (3u * STGB)            // 110592
#define HROWB 272u                   // 128 halves data + pad
#define SMEM_BYTES (110592 + 128 * 272)   // 145408

// ---------------- PTX helpers ----------------
__device__ __forceinline__ uint32_t smem_u32(const void* p) {
    uint32_t a;
    asm("{ .reg .u64 t; cvta.to.shared.u64 t, %1; cvt.u32.u64 %0, t; }" : "=r"(a) : "l"(p));
    return a;
}
__device__ __forceinline__ void cpasync16(uint32_t s, const void* g) {
    asm volatile("cp.async.cg.shared.global [%0], [%1], 16;" :: "r"(s), "l"(g));
}
#define CP_COMMIT() asm volatile("cp.async.commit_group;")
#define CP_WAIT1()  asm volatile("cp.async.wait_group 1;")
#define CP_WAIT0()  asm volatile("cp.async.wait_group 0;")

#define LDSM4(r0, r1, r2, r3, addr) \
    asm volatile("ldmatrix.sync.aligned.m8n8.x4.shared.b16 {%0,%1,%2,%3}, [%4];" \
        : "=r"(r0), "=r"(r1), "=r"(r2), "=r"(r3) : "r"(addr))

__device__ __forceinline__ void mma16(float* d, const uint32_t* a,
                                      uint32_t b0, uint32_t b1) {
    asm volatile(
        "mma.sync.aligned.m16n8k16.row.col.f32.f16.f16.f32 "
        "{%0,%1,%2,%3}, {%4,%5,%6,%7}, {%8,%9}, {%0,%1,%2,%3};"
        : "+f"(d[0]), "+f"(d[1]), "+f"(d[2]), "+f"(d[3])
        : "r"(a[0]), "r"(a[1]), "r"(a[2]), "r"(a[3]), "r"(b0), "r"(b1));
}

__device__ __forceinline__ uint32_t h2u(__half2 h) {
    return *(uint32_t*)&h;   // register-level reinterpret
}

// ---------------- merged prep kernel (one launch, bandwidth-optimal) ----------
// Blocks (256 threads each):
//   [0, 4096)     : xr   — 8 floats/thread, float4 in -> uint4(8 half) out
//   [4096, 4352)  : w1t  — 64x64 smem tile transpose (nb 0..31, nc 0..7)
//   [4352, 4384)  : w2t  — 64x64 smem tile transpose (hb 0..7,  nb 0..3)
//   [4384, 4896)  : c1   — one block per s
//   [4896, 4960)  : zero g_m (uint4)
#define PREP_BLOCKS 4960
__global__ void prep_all_kernel(const float* __restrict__ x,
                                const float* __restrict__ W1,
                                const float* __restrict__ b1,
                                const float* __restrict__ W2,
                                const float* __restrict__ dist) {
    __shared__ float tsm[64][65];
    const int blk = blockIdx.x, t = threadIdx.x;

    if (blk < 4096) {
        // xr: thread handles 8 consecutive floats
        const int u = blk * 256 + t;
        float4 a = ((const float4*)x)[2 * u];
        float4 b = ((const float4*)x)[2 * u + 1];
        uint4 o;
        o.x = h2u(__floats2half2_rn(a.x, a.y));
        o.y = h2u(__floats2half2_rn(a.z, a.w));
        o.z = h2u(__floats2half2_rn(b.x, b.y));
        o.w = h2u(__floats2half2_rn(b.z, b.w));
        ((uint4*)g_xr)[u] = o;
    } else if (blk < 4352) {
        // w1t: transpose W1 block rows [nb*65, +64), cols [nc*64, +64)
        const int q = blk - 4096;
        const int nb = q >> 3, nc = q & 7;
        const int rbase = nb * 65, cbase = nc * 64;
        const int rr = t >> 6, cc = t & 63;   // 4 rows per pass
#pragma unroll
        for (int p = 0; p < 16; p++) {
            int f = p * 4 + rr;
            tsm[f][cc] = W1[(size_t)(rbase + f) * H1n + cbase + cc];
        }
        __syncthreads();
        // write g_w1t[n][k]: n = cbase + nl, k = nb*64 + f (f = cc contiguous)
#pragma unroll
        for (int p = 0; p < 16; p++) {
            int nl = p * 4 + rr;
            g_w1t[(size_t)(cbase + nl) * 2048 + nb * 64 + cc] =
                __float2half_rn(tsm[cc][nl]);
        }
    } else if (blk < 4384) {
        // w2t: transpose W2 block rows(h) [hb*64, +64), cols(n) [nbq*64, +64)
        const int q = blk - 4352;
        const int hb = q >> 2, nbq = q & 3;
        const int hbase = hb * 64, nbase = nbq * 64;
        const int rr = t >> 6, cc = t & 63;
#pragma unroll
        for (int p = 0; p < 16; p++) {
            int h = p * 4 + rr;
            tsm[h][cc] = W2[(size_t)(hbase + h) * H2n + nbase + cc];
        }
        __syncthreads();
#pragma unroll
        for (int p = 0; p < 16; p++) {
            int nl = p * 4 + rr;
            g_w2t[(size_t)(nbase + nl) * H1n + hbase + cc] =
                __float2half_rn(tsm[cc][nl]);
        }
    } else if (blk < 4896) {
        const int s = blk - 4384;
#pragma unroll
        for (int hh = 0; hh < 2; hh++) {
            int h = t + hh * 256;
            float acc = b1[h];
#pragma unroll
            for (int k = 0; k < Kn; k++)
                acc = fmaf(dist[s * Kn + k], W1[(k * 65 + 64) * H1n + h], acc);
            g_c1[s * H1n + h] = acc;
        }
    } else {
        const int i = (blk - 4896) * 256 + t;   // uint4 index, 16384 total
        ((uint4*)g_m)[i] = make_uint4(0u, 0u, 0u, 0u);
    }
}

// ---------------- load helpers (256 threads) — R8/R13 verbatim ----------------
__device__ __forceinline__ void issue_g1(int c, int n1, int st, int tid,
                                         uint32_t smb, const int* __restrict__ nbh_s,
                                         int b0) {
    const int sidx = __ldg(&nbh_s[c]);
    const uint32_t ab = smb + (uint32_t)st * STGB;
    const __half* asrc = g_xr + ((size_t)b0 * Sn + sidx) * Fn;
#pragma unroll
    for (int p = 0; p < 4; p++) {
        int u = tid + p * 256; int r = u >> 3, q = u & 7;
        cpasync16(ab + (uint32_t)r * ROWB + (uint32_t)q * 16u,
                  asrc + (size_t)r * (Sn * Fn) + q * 8);
    }
    const uint32_t bb = ab + TILEB;
    const __half* bsrc = g_w1t + (size_t)(n1 * 128) * 2048 + c * 64;
#pragma unroll
    for (int p = 0; p < 4; p++) {
        int u = tid + p * 256; int r = u >> 3, q = u & 7;
        cpasync16(bb + (uint32_t)r * ROWB + (uint32_t)q * 16u,
                  bsrc + (size_t)r * 2048 + q * 8);
    }
}
__device__ __forceinline__ void issue_g2(int n1, int hk, int st, int tid,
                                         uint32_t smb) {
    const uint32_t bb = smb + (uint32_t)st * STGB;
    const __half* bsrc = g_w2t + n1 * 128 + hk * 64;
#pragma unroll
    for (int p = 0; p < 8; p++) {
        int u = tid + p * 256; int n = u >> 3, q = u & 7;
        cpasync16(bb + (uint32_t)n * ROWB + (uint32_t)q * 16u,
                  bsrc + (size_t)n * H1n + q * 8);
    }
}

// ---------------- fused fp16 mma kernel — R8/R13 verbatim ----------------
__global__ __launch_bounds__(256, 1)
void fused_mma_kernel(const int* __restrict__ nbh, const float* __restrict__ b2) {
    extern __shared__ char smc[];
    const int tid = threadIdx.x, lane = tid & 31, wid = tid >> 5;
    const int gid = lane >> 2, tig = lane & 3;
    const int wm = (wid >> 1) * 32;
    const int wn = wid & 1;
    const int s = blockIdx.y, b0 = blockIdx.x * 128;
    const int* nbh_s = nbh + s * Kn;
    const uint32_t smb = smem_u32(smc);

    const uint32_t a_lrow = (uint32_t)(lane & 15) * ROWB + (uint32_t)(lane >> 4) * 16u;
    const int bg = lane >> 3;
    const uint32_t b_lrow = (uint32_t)(((bg >> 1) * 8) + (lane & 7)) * ROWB
                          + (uint32_t)(bg & 1) * 16u;
    const uint32_t h_lrow = (uint32_t)(lane & 15) * HROWB + (uint32_t)(lane >> 4) * 16u;

    float acc2[2][16][4];
#pragma unroll
    for (int mt = 0; mt < 2; mt++)
#pragma unroll
        for (int nt = 0; nt < 16; nt++)
#pragma unroll
            for (int i = 0; i < 4; i++) acc2[mt][nt][i] = 0.f;

    for (int n1 = 0; n1 < 4; n1++) {
        float acc1[2][8][4];
#pragma unroll
        for (int mt = 0; mt < 2; mt++)
#pragma unroll
            for (int nt = 0; nt < 8; nt++)
#pragma unroll
                for (int i = 0; i < 4; i++) acc1[mt][nt][i] = 0.f;

        __syncthreads();
        issue_g1(0, n1, 0, tid, smb, nbh_s, b0);
        CP_COMMIT();
        issue_g1(1, n1, 1, tid, smb, nbh_s, b0);
        CP_COMMIT();

        for (int c = 0; c < 32; c++) {
            CP_WAIT1();
            __syncthreads();
            if (c < 30)       issue_g1(c + 2, n1, (c + 2) % 3, tid, smb, nbh_s, b0);
            else if (c == 30) issue_g2(n1, 0, 2, tid, smb);
            else              issue_g2(n1, 1, 0, tid, smb);
            CP_COMMIT();

            const uint32_t stb = smb + (uint32_t)(c % 3) * STGB;
            const uint32_t aT = stb + (uint32_t)wm * ROWB + a_lrow;
            const uint32_t bT = stb + TILEB + (uint32_t)(wn * 64) * ROWB + b_lrow;
#pragma unroll
            for (int ks = 0; ks < 4; ks++) {
                uint32_t a0[4], a1[4];
                LDSM4(a0[0], a0[1], a0[2], a0[3], aT + ks * 32);
                LDSM4(a1[0], a1[1], a1[2], a1[3], aT + 16 * ROWB + ks * 32);
#pragma unroll
                for (int j = 0; j < 4; j++) {
                    uint32_t r0, r1, r2, r3;
                    LDSM4(r0, r1, r2, r3, bT + (uint32_t)j * (16 * ROWB) + ks * 32);
                    mma16(acc1[0][2 * j],     a0, r0, r1);
                    mma16(acc1[0][2 * j + 1], a0, r2, r3);
                    mma16(acc1[1][2 * j],     a1, r0, r1);
                    mma16(acc1[1][2 * j + 1], a1, r2, r3);
                }
            }
        }

        {
            const float* c1p = g_c1 + s * H1n + n1 * 128;
#pragma unroll
            for (int nt = 0; nt < 8; nt++) {
                const int col = wn * 64 + nt * 8 + tig * 2;
                const float2 cv = __ldg((const float2*)(c1p + col));
#pragma unroll
                for (int mt = 0; mt < 2; mt++) {
                    const int r = wm + mt * 16 + gid;
                    __half2* h0 = (__half2*)(smc + HS_B + (uint32_t)r * HROWB + col * 2);
                    __half2* h1r = (__half2*)(smc + HS_B + (uint32_t)(r + 8) * HROWB + col * 2);
                    *h0  = __floats2half2_rn(fmaxf(acc1[mt][nt][0] + cv.x, 0.f),
                                             fmaxf(acc1[mt][nt][1] + cv.y, 0.f));
                    *h1r = __floats2half2_rn(fmaxf(acc1[mt][nt][2] + cv.x, 0.f),
                                             fmaxf(acc1[mt][nt][3] + cv.y, 0.f));
                }
            }
        }

#pragma unroll
        for (int kc = 0; kc < 2; kc++) {
            if (kc == 0) CP_WAIT1(); else CP_WAIT0();
            __syncthreads();
            const uint32_t aT = smb + HS_B + (uint32_t)wm * HROWB + h_lrow
                              + (uint32_t)kc * 128u;
            const uint32_t bT = smb + (uint32_t)(kc == 0 ? 2 : 0) * STGB
                              + (uint32_t)(wn * 128) * ROWB + b_lrow;
#pragma unroll
            for (int ks = 0; ks < 4; ks++) {
                uint32_t a0[4], a1[4];
                LDSM4(a0[0], a0[1], a0[2], a0[3], aT + ks * 32);
                LDSM4(a1[0], a1[1], a1[2], a1[3], aT + 16 * HROWB + ks * 32);
#pragma unroll
                for (int j = 0; j < 8; j++) {
                    uint32_t r0, r1, r2, r3;
                    LDSM4(r0, r1, r2, r3, bT + (uint32_t)j * (16 * ROWB) + ks * 32);
                    mma16(acc2[0][2 * j],     a0, r0, r1);
                    mma16(acc2[0][2 * j + 1], a0, r2, r3);
                    mma16(acc2[1][2 * j],     a1, r0, r1);
                    mma16(acc2[1][2 * j + 1], a1, r2, r3);
                }
            }
        }
    }

#pragma unroll
    for (int nt = 0; nt < 16; nt++) {
        const int n2 = wn * 128 + nt * 8 + tig * 2;
        const float2 bv = __ldg((const float2*)(b2 + n2));
#pragma unroll
        for (int mt = 0; mt < 2; mt++) {
            const int r = b0 + wm + mt * 16 + gid;
            float v0 = fmaxf(acc2[mt][nt][0] + bv.x, 0.f);
            float v1 = fmaxf(acc2[mt][nt][1] + bv.y, 0.f);
            float v2 = fmaxf(acc2[mt][nt][2] + bv.x, 0.f);
            float v3 = fmaxf(acc2[mt][nt][3] + bv.y, 0.f);
            atomicMax(&g_m[r * H2n + n2],           __float_as_uint(v0));
            atomicMax(&g_m[r * H2n + n2 + 1],       __float_as_uint(v1));
            atomicMax(&g_m[(r + 8) * H2n + n2],     __float_as_uint(v2));
            atomicMax(&g_m[(r + 8) * H2n + n2 + 1], __float_as_uint(v3));
        }
    }
}

// ---------------- finalize ----------------
__global__ void finalize_kernel(const float* __restrict__ Wd,
                                const float* __restrict__ bd,
                                float* __restrict__ out) {
    __shared__ float red[256];
    const int b = blockIdx.x, t = threadIdx.x;
    red[t] = __uint_as_float(g_m[b * H2n + t]) * Wd[t];
    __syncthreads();
#pragma unroll
    for (int st = 128; st > 0; st >>= 1) {
        if (t < st) red[t] += red[t + st];
        __syncthreads();
    }
    if (t == 0) out[b] = red[0] + bd[0];
}

extern "C" void kernel_launch(void* const* d_in, const int* in_sizes, int n_in,
                              void* d_out, int out_size) {
    const float* x    = (const float*)d_in[0];
    const int*   nbh  = (const int*)  d_in[1];
    const float* dist = (const float*)d_in[2];
    const float* W1   = (const float*)d_in[3];
    const float* b1   = (const float*)d_in[4];
    const float* W2   = (const float*)d_in[5];
    const float* b2   = (const float*)d_in[6];
    const float* Wd   = (const float*)d_in[7];
    const float* bd   = (const float*)d_in[8];
    float* out = (float*)d_out;

    static bool attr_set = false;
    if (!attr_set) {
        cudaFuncSetAttribute(fused_mma_kernel,
                             cudaFuncAttributeMaxDynamicSharedMemorySize, SMEM_BYTES);
        attr_set = true;
    }

    prep_all_kernel<<<PREP_BLOCKS, 256>>>(x, W1, b1, W2, dist);
    fused_mma_kernel<<<dim3(2, Sn), 256, SMEM_BYTES>>>(nbh, b2);
    finalize_kernel<<<Bn, H2n>>>(Wd, bd, out);
}

// round 16
// speedup vs baseline: 1.2747x; 1.0007x over previous
#include <cuda_runtime.h>
#include <cuda_fp16.h>
#include <cstdint>

#define Bn 256
#define Sn 512
#define Kn 32
#define Fn 64
#define H1n 512
#define H2n 256

// ---------------- device scratch (allocation-free rule) ----------------
__device__ float    g_c1[Sn * H1n];        // fp32: b1 + dist-column contribution
__device__ unsigned g_m[Bn * H2n];         // bits of max_s relu(h2)
__device__ __half   g_w1t[H1n * 2048];     // [n][k], k = nb*64+f, fp16
__device__ __half   g_w2t[H2n * H1n];      // [n2][h1], fp16
__device__ __half   g_xr[Bn * Sn * Fn];    // fp16 x

// ---------------- smem layout (bytes) ----------------
#define ROWB 144u
#define TILEB (128u * ROWB)          // 18432
#define STGB  (2u * TILEB)           // 36864 per stage (A at +0, B at +TILEB)
#define HS_B  (3u * STGB)            // 110592
#define HROWB 272u                   // 128 halves data + pad
#define SMEM_BYTES (110592 + 128 * 272)   // 145408

// ---------------- PTX helpers ----------------
__device__ __forceinline__ uint32_t smem_u32(const void* p) {
    uint32_t a;
    asm("{ .reg .u64 t; cvta.to.shared.u64 t, %1; cvt.u32.u64 %0, t; }" : "=r"(a) : "l"(p));
    return a;
}
__device__ __forceinline__ void cpasync16(uint32_t s, const void* g) {
    asm volatile("cp.async.cg.shared.global [%0], [%1], 16;" :: "r"(s), "l"(g));
}
#define CP_COMMIT() asm volatile("cp.async.commit_group;")
#define CP_WAIT1()  asm volatile("cp.async.wait_group 1;")
#define CP_WAIT0()  asm volatile("cp.async.wait_group 0;")

#define LDSM4(r0, r1, r2, r3, addr) \
    asm volatile("ldmatrix.sync.aligned.m8n8.x4.shared.b16 {%0,%1,%2,%3}, [%4];" \
        : "=r"(r0), "=r"(r1), "=r"(r2), "=r"(r3) : "r"(addr))

__device__ __forceinline__ void mma16(float* d, const uint32_t* a,
                                      uint32_t b0, uint32_t b1) {
    asm volatile(
        "mma.sync.aligned.m16n8k16.row.col.f32.f16.f16.f32 "
        "{%0,%1,%2,%3}, {%4,%5,%6,%7}, {%8,%9}, {%0,%1,%2,%3};"
        : "+f"(d[0]), "+f"(d[1]), "+f"(d[2]), "+f"(d[3])
        : "r"(a[0]), "r"(a[1]), "r"(a[2]), "r"(a[3]), "r"(b0), "r"(b1));
}

__device__ __forceinline__ uint32_t h2u(__half2 h) {
    return *(uint32_t*)&h;   // register-level reinterpret
}

// ---------------- merged prep kernel (one launch) ----------------
// Small/latency-bound work gets the LOWEST block ids so it overlaps the
// xr streaming bulk instead of trailing it:
//   [0, 512)      : c1   — one block per s
//   [512, 768)    : w1t  — 64x64 smem tile transpose (nb 0..31, nc 0..7)
//   [768, 800)    : w2t  — 64x64 smem tile transpose (hb 0..7,  nb 0..3)
//   [800, 864)    : zero g_m (uint4)
//   [864, 4960)   : xr   — 8 floats/thread, float4 in -> uint4(8 half) out
#define PREP_BLOCKS 4960
__global__ void prep_all_kernel(const float* __restrict__ x,
                                const float* __restrict__ W1,
                                const float* __restrict__ b1,
                                const float* __restrict__ W2,
                                const float* __restrict__ dist) {
    __shared__ float tsm[64][65];
    const int blk = blockIdx.x, t = threadIdx.x;

    if (blk >= 864) {
        // xr: thread handles 8 consecutive floats
        const int u = (blk - 864) * 256 + t;
        float4 a = ((const float4*)x)[2 * u];
        float4 b = ((const float4*)x)[2 * u + 1];
        uint4 o;
        o.x = h2u(__floats2half2_rn(a.x, a.y));
        o.y = h2u(__floats2half2_rn(a.z, a.w));
        o.z = h2u(__floats2half2_rn(b.x, b.y));
        o.w = h2u(__floats2half2_rn(b.z, b.w));
        ((uint4*)g_xr)[u] = o;
    } else if (blk < 512) {
        const int s = blk;
#pragma unroll
        for (int hh = 0; hh < 2; hh++) {
            int h = t + hh * 256;
            float acc = b1[h];
#pragma unroll
            for (int k = 0; k < Kn; k++)
                acc = fmaf(dist[s * Kn + k], W1[(k * 65 + 64) * H1n + h], acc);
            g_c1[s * H1n + h] = acc;
        }
    } else if (blk < 768) {
        // w1t: transpose W1 block rows [nb*65, +64), cols [nc*64, +64)
        const int q = blk - 512;
        const int nb = q >> 3, nc = q & 7;
        const int rbase = nb * 65, cbase = nc * 64;
        const int rr = t >> 6, cc = t & 63;   // 4 rows per pass
#pragma unroll
        for (int p = 0; p < 16; p++) {
            int f = p * 4 + rr;
            tsm[f][cc] = W1[(size_t)(rbase + f) * H1n + cbase + cc];
        }
        __syncthreads();
        // write g_w1t[n][k]: n = cbase + nl, k = nb*64 + f (f = cc contiguous)
#pragma unroll
        for (int p = 0; p < 16; p++) {
            int nl = p * 4 + rr;
            g_w1t[(size_t)(cbase + nl) * 2048 + nb * 64 + cc] =
                __float2half_rn(tsm[cc][nl]);
        }
    } else if (blk < 800) {
        // w2t: transpose W2 block rows(h) [hb*64, +64), cols(n) [nbq*64, +64)
        const int q = blk - 768;
        const int hb = q >> 2, nbq = q & 3;
        const int hbase = hb * 64, nbase = nbq * 64;
        const int rr = t >> 6, cc = t & 63;
#pragma unroll
        for (int p = 0; p < 16; p++) {
            int h = p * 4 + rr;
            tsm[h][cc] = W2[(size_t)(hbase + h) * H2n + nbase + cc];
        }
        __syncthreads();
#pragma unroll
        for (int p = 0; p < 16; p++) {
            int nl = p * 4 + rr;
            g_w2t[(size_t)(nbase + nl) * H1n + hbase + cc] =
                __float2half_rn(tsm[cc][nl]);
        }
    } else {
        const int i = (blk - 800) * 256 + t;   // uint4 index, 16384 total
        ((uint4*)g_m)[i] = make_uint4(0u, 0u, 0u, 0u);
    }
}

// ---------------- load helpers (256 threads) — R8/R13 verbatim ----------------
__device__ __forceinline__ void issue_g1(int c, int n1, int st, int tid,
                                         uint32_t smb, const int* __restrict__ nbh_s,
                                         int b0) {
    const int sidx = __ldg(&nbh_s[c]);
    const uint32_t ab = smb + (uint32_t)st * STGB;
    const __half* asrc = g_xr + ((size_t)b0 * Sn + sidx) * Fn;
#pragma unroll
    for (int p = 0; p < 4; p++) {
        int u = tid + p * 256; int r = u >> 3, q = u & 7;
        cpasync16(ab + (uint32_t)r * ROWB + (uint32_t)q * 16u,
                  asrc + (size_t)r * (Sn * Fn) + q * 8);
    }
    const uint32_t bb = ab + TILEB;
    const __half* bsrc = g_w1t + (size_t)(n1 * 128) * 2048 + c * 64;
#pragma unroll
    for (int p = 0; p < 4; p++) {
        int u = tid + p * 256; int r = u >> 3, q = u & 7;
        cpasync16(bb + (uint32_t)r * ROWB + (uint32_t)q * 16u,
                  bsrc + (size_t)r * 2048 + q * 8);
    }
}
__device__ __forceinline__ void issue_g2(int n1, int hk, int st, int tid,
                                         uint32_t smb) {
    const uint32_t bb = smb + (uint32_t)st * STGB;
    const __half* bsrc = g_w2t + n1 * 128 + hk * 64;
#pragma unroll
    for (int p = 0; p < 8; p++) {
        int u = tid + p * 256; int n = u >> 3, q = u & 7;
        cpasync16(bb + (uint32_t)n * ROWB + (uint32_t)q * 16u,
                  bsrc + (size_t)n * H1n + q * 8);
    }
}

// ---------------- fused fp16 mma kernel — R8/R13 verbatim ----------------
__global__ __launch_bounds__(256, 1)
void fused_mma_kernel(const int* __restrict__ nbh, const float* __restrict__ b2) {
    extern __shared__ char smc[];
    const int tid = threadIdx.x, lane = tid & 31, wid = tid >> 5;
    const int gid = lane >> 2, tig = lane & 3;
    const int wm = (wid >> 1) * 32;
    const int wn = wid & 1;
    const int s = blockIdx.y, b0 = blockIdx.x * 128;
    const int* nbh_s = nbh + s * Kn;
    const uint32_t smb = smem_u32(smc);

    const uint32_t a_lrow = (uint32_t)(lane & 15) * ROWB + (uint32_t)(lane >> 4) * 16u;
    const int bg = lane >> 3;
    const uint32_t b_lrow = (uint32_t)(((bg >> 1) * 8) + (lane & 7)) * ROWB
                          + (uint32_t)(bg & 1) * 16u;
    const uint32_t h_lrow = (uint32_t)(lane & 15) * HROWB + (uint32_t)(lane >> 4) * 16u;

    float acc2[2][16][4];
#pragma unroll
    for (int mt = 0; mt < 2; mt++)
#pragma unroll
        for (int nt = 0; nt < 16; nt++)
#pragma unroll
            for (int i = 0; i < 4; i++) acc2[mt][nt][i] = 0.f;

    for (int n1 = 0; n1 < 4; n1++) {
        float acc1[2][8][4];
#pragma unroll
        for (int mt = 0; mt < 2; mt++)
#pragma unroll
            for (int nt = 0; nt < 8; nt++)
#pragma unroll
                for (int i = 0; i < 4; i++) acc1[mt][nt][i] = 0.f;

        __syncthreads();
        issue_g1(0, n1, 0, tid, smb, nbh_s, b0);
        CP_COMMIT();
        issue_g1(1, n1, 1, tid, smb, nbh_s, b0);
        CP_COMMIT();

        for (int c = 0; c < 32; c++) {
            CP_WAIT1();
            __syncthreads();
            if (c < 30)       issue_g1(c + 2, n1, (c + 2) % 3, tid, smb, nbh_s, b0);
            else if (c == 30) issue_g2(n1, 0, 2, tid, smb);
            else              issue_g2(n1, 1, 0, tid, smb);
            CP_COMMIT();

            const uint32_t stb = smb + (uint32_t)(c % 3) * STGB;
            const uint32_t aT = stb + (uint32_t)wm * ROWB + a_lrow;
            const uint32_t bT = stb + TILEB + (uint32_t)(wn * 64) * ROWB + b_lrow;
#pragma unroll
            for (int ks = 0; ks < 4; ks++) {
                uint32_t a0[4], a1[4];
                LDSM4(a0[0], a0[1], a0[2], a0[3], aT + ks * 32);
                LDSM4(a1[0], a1[1], a1[2], a1[3], aT + 16 * ROWB + ks * 32);
#pragma unroll
                for (int j = 0; j < 4; j++) {
                    uint32_t r0, r1, r2, r3;
                    LDSM4(r0, r1, r2, r3, bT + (uint32_t)j * (16 * ROWB) + ks * 32);
                    mma16(acc1[0][2 * j],     a0, r0, r1);
                    mma16(acc1[0][2 * j + 1], a0, r2, r3);
                    mma16(acc1[1][2 * j],     a1, r0, r1);
                    mma16(acc1[1][2 * j + 1], a1, r2, r3);
                }
            }
        }

        {
            const float* c1p = g_c1 + s * H1n + n1 * 128;
#pragma unroll
            for (int nt = 0; nt < 8; nt++) {
                const int col = wn * 64 + nt * 8 + tig * 2;
                const float2 cv = __ldg((const float2*)(c1p + col));
#pragma unroll
                for (int mt = 0; mt < 2; mt++) {
                    const int r = wm + mt * 16 + gid;
                    __half2* h0 = (__half2*)(smc + HS_B + (uint32_t)r * HROWB + col * 2);
                    __half2* h1r = (__half2*)(smc + HS_B + (uint32_t)(r + 8) * HROWB + col * 2);
                    *h0  = __floats2half2_rn(fmaxf(acc1[mt][nt][0] + cv.x, 0.f),
                                             fmaxf(acc1[mt][nt][1] + cv.y, 0.f));
                    *h1r = __floats2half2_rn(fmaxf(acc1[mt][nt][2] + cv.x, 0.f),
                                             fmaxf(acc1[mt][nt][3] + cv.y, 0.f));
                }
            }
        }

#pragma unroll
        for (int kc = 0; kc < 2; kc++) {
            if (kc == 0) CP_WAIT1(); else CP_WAIT0();
            __syncthreads();
            const uint32_t aT = smb + HS_B + (uint32_t)wm * HROWB + h_lrow
                              + (uint32_t)kc * 128u;
            const uint32_t bT = smb + (uint32_t)(kc == 0 ? 2 : 0) * STGB
                              + (uint32_t)(wn * 128) * ROWB + b_lrow;
#pragma unroll
            for (int ks = 0; ks < 4; ks++) {
                uint32_t a0[4], a1[4];
                LDSM4(a0[0], a0[1], a0[2], a0[3], aT + ks * 32);
                LDSM4(a1[0], a1[1], a1[2], a1[3], aT + 16 * HROWB + ks * 32);
#pragma unroll
                for (int j = 0; j < 8; j++) {
                    uint32_t r0, r1, r2, r3;
                    LDSM4(r0, r1, r2, r3, bT + (uint32_t)j * (16 * ROWB) + ks * 32);
                    mma16(acc2[0][2 * j],     a0, r0, r1);
                    mma16(acc2[0][2 * j + 1], a0, r2, r3);
                    mma16(acc2[1][2 * j],     a1, r0, r1);
                    mma16(acc2[1][2 * j + 1], a1, r2, r3);
                }
            }
        }
    }

#pragma unroll
    for (int nt = 0; nt < 16; nt++) {
        const int n2 = wn * 128 + nt * 8 + tig * 2;
        const float2 bv = __ldg((const float2*)(b2 + n2));
#pragma unroll
        for (int mt = 0; mt < 2; mt++) {
            const int r = b0 + wm + mt * 16 + gid;
            float v0 = fmaxf(acc2[mt][nt][0] + bv.x, 0.f);
            float v1 = fmaxf(acc2[mt][nt][1] + bv.y, 0.f);
            float v2 = fmaxf(acc2[mt][nt][2] + bv.x, 0.f);
            float v3 = fmaxf(acc2[mt][nt][3] + bv.y, 0.f);
            atomicMax(&g_m[r * H2n + n2],           __float_as_uint(v0));
            atomicMax(&g_m[r * H2n + n2 + 1],       __float_as_uint(v1));
            atomicMax(&g_m[(r + 8) * H2n + n2],     __float_as_uint(v2));
            atomicMax(&g_m[(r + 8) * H2n + n2 + 1], __float_as_uint(v3));
        }
    }
}

// ---------------- finalize ----------------
__global__ void finalize_kernel(const float* __restrict__ Wd,
                                const float* __restrict__ bd,
                                float* __restrict__ out) {
    __shared__ float red[256];
    const int b = blockIdx.x, t = threadIdx.x;
    red[t] = __uint_as_float(g_m[b * H2n + t]) * Wd[t];
    __syncthreads();
#pragma unroll
    for (int st = 128; st > 0; st >>= 1) {
        if (t < st) red[t] += red[t + st];
        __syncthreads();
    }
    if (t == 0) out[b] = red[0] + bd[0];
}

extern "C" void kernel_launch(void* const* d_in, const int* in_sizes, int n_in,
                              void* d_out, int out_size) {
    const float* x    = (const float*)d_in[0];
    const int*   nbh  = (const int*)  d_in[1];
    const float* dist = (const float*)d_in[2];
    const float* W1   = (const float*)d_in[3];
    const float* b1   = (const float*)d_in[4];
    const float* W2   = (const float*)d_in[5];
    const float* b2   = (const float*)d_in[6];
    const float* Wd   = (const float*)d_in[7];
    const float* bd   = (const float*)d_in[8];
    float* out = (float*)d_out;

    static bool attr_set = false;
    if (!attr_set) {
        cudaFuncSetAttribute(fused_mma_kernel,
                             cudaFuncAttributeMaxDynamicSharedMemorySize, SMEM_BYTES);
        attr_set = true;
    }

    prep_all_kernel<<<PREP_BLOCKS, 256>>>(x, W1, b1, W2, dist);
    fused_mma_kernel<<<dim3(2, Sn), 256, SMEM_BYTES>>>(nbh, b2);
    finalize_kernel<<<Bn, H2n>>>(Wd, bd, out);
}